// round 1
// baseline (speedup 1.0000x reference)
#include <cuda_runtime.h>
#include <cstdint>

// Problem constants
constexpr int Tt = 1024;   // timesteps
constexpr int Bb = 128;    // batch
constexpr int Ii = 256;    // input dim
constexpr int Hh = 512;    // hidden dim
constexpr long long TBH = (long long)Tt * Bb * Hh;   // output region size

// -------------------------------------------------------------------------
// accurate-enough tanh that survives --use_fast_math
// tanh(x) = sign(x) * (1 - e) / (1 + e),  e = exp(-2|x|)  (e in (0,1], no overflow)
// -------------------------------------------------------------------------
__device__ __forceinline__ float tanh_acc(float x) {
    float ax = fabsf(x);
    float e  = __expf(-2.0f * ax);
    float r  = (1.0f - e) / (1.0f + e);
    return copysignf(r, x);
}

// =========================================================================
// Kernel 1: xw = x @ Wi^T   written in-place into d_out[0 : T*B*H)
//   C[m, n] = sum_k x[m, k] * Wi[n, k],  M = T*B = 131072, N = 512, K = 256
//   CTA tile 128x128, K-chunks of 32, 256 threads, 8x8 micro-tiles.
// =========================================================================
__global__ void __launch_bounds__(256, 2)
xw_gemm_kernel(const float* __restrict__ x,
               const float* __restrict__ Wi,
               float* __restrict__ out)
{
    __shared__ float As[32][132];   // [k][m], padded
    __shared__ float Bs[32][132];   // [k][n], padded

    const int m0 = (blockIdx.x >> 2) * 128;   // 1024 m-tiles
    const int n0 = (blockIdx.x & 3) * 128;    // 4 n-tiles
    const int tid = threadIdx.x;
    const int mt = tid >> 4;                  // 0..15
    const int nt = tid & 15;                  // 0..15

    float acc[8][8];
    #pragma unroll
    for (int i = 0; i < 8; i++)
        #pragma unroll
        for (int j = 0; j < 8; j++) acc[i][j] = 0.0f;

    for (int k0 = 0; k0 < Ii; k0 += 32) {
        // load 128x32 tiles of A (x) and B (Wi), store transposed [k][row]
        #pragma unroll
        for (int r = 0; r < 4; r++) {
            int f   = tid + r * 256;          // float4 index 0..1023
            int row = f >> 3;                 // 0..127
            int kq  = (f & 7) << 2;           // 0,4,...,28
            float4 va = *reinterpret_cast<const float4*>(
                &x[(size_t)(m0 + row) * Ii + k0 + kq]);
            As[kq + 0][row] = va.x; As[kq + 1][row] = va.y;
            As[kq + 2][row] = va.z; As[kq + 3][row] = va.w;
            float4 vb = *reinterpret_cast<const float4*>(
                &Wi[(size_t)(n0 + row) * Ii + k0 + kq]);
            Bs[kq + 0][row] = vb.x; Bs[kq + 1][row] = vb.y;
            Bs[kq + 2][row] = vb.z; Bs[kq + 3][row] = vb.w;
        }
        __syncthreads();

        #pragma unroll 8
        for (int kk = 0; kk < 32; kk++) {
            float a[8], b[8];
            *reinterpret_cast<float4*>(a)     = *reinterpret_cast<const float4*>(&As[kk][mt * 8]);
            *reinterpret_cast<float4*>(a + 4) = *reinterpret_cast<const float4*>(&As[kk][mt * 8 + 4]);
            *reinterpret_cast<float4*>(b)     = *reinterpret_cast<const float4*>(&Bs[kk][nt * 8]);
            *reinterpret_cast<float4*>(b + 4) = *reinterpret_cast<const float4*>(&Bs[kk][nt * 8 + 4]);
            #pragma unroll
            for (int i = 0; i < 8; i++)
                #pragma unroll
                for (int j = 0; j < 8; j++)
                    acc[i][j] += a[i] * b[j];
        }
        __syncthreads();
    }

    // store 8x8 tile
    #pragma unroll
    for (int i = 0; i < 8; i++) {
        size_t g = (size_t)(m0 + mt * 8 + i) * Hh + n0 + nt * 8;
        float4 v0 = make_float4(acc[i][0], acc[i][1], acc[i][2], acc[i][3]);
        float4 v1 = make_float4(acc[i][4], acc[i][5], acc[i][6], acc[i][7]);
        *reinterpret_cast<float4*>(&out[g])     = v0;
        *reinterpret_cast<float4*>(&out[g + 4]) = v1;
    }
}

// =========================================================================
// Kernel 2: recurrent scan, in place on d_out.
//   16 clusters x 8 CTAs. Cluster c owns batch rows [c*8, c*8+8).
//   CTA rank r in its cluster owns output columns [r*64, r*64+64) and holds
//   that 64x512 slice of Wh in smem (transposed, [k][j]).
//   h_{t-1} lives in d_out[t-1] (written by all 8 CTAs of the cluster);
//   barrier.cluster (release/acquire + L1 invalidate) orders the exchange.
//   Thread layout: tid = kg*32 + bt*16 + jt  (kg:8 k-groups, bt:2, jt:16)
//   per-thread micro-tile: 4 b-rows x 4 j-cols over a 64-wide k range.
// =========================================================================
constexpr int W_S_ELEMS = Hh * 64;        // 32768 (w_s[k][64])
constexpr int H_S_PITCH = Hh + 4;         // 516, padded row per batch row
constexpr int H_S_ELEMS = 8 * H_S_PITCH;  // 4128
constexpr int RED_ELEMS = 8 * 512;        // 4096 (red[kg][o])
constexpr int SCAN_SMEM_BYTES = (W_S_ELEMS + H_S_ELEMS + RED_ELEMS) * 4; // 163968

__global__ void __cluster_dims__(8, 1, 1) __launch_bounds__(256, 1)
rnn_scan_kernel(const float* __restrict__ Wh, float* __restrict__ out)
{
    extern __shared__ float smem[];
    float* w_s = smem;                       // [512][64]  (k-major)
    float* h_s = w_s + W_S_ELEMS;            // [8][516]   (b-major, padded)
    float* red = h_s + H_S_ELEMS;            // [8][512]   (kg-major)

    const int tid  = threadIdx.x;
    const int cid  = blockIdx.x >> 3;        // cluster id, 0..15
    const int rank = blockIdx.x & 7;         // rank in cluster, 0..7
    const int b0   = cid * 8;                // batch rows of this cluster
    const int j0   = rank * 64;              // output columns of this CTA

    // ---- one-time: load Wh slice transposed into smem: w_s[k][jl] = Wh[j0+jl][k]
    for (int f = tid; f < 64 * 128; f += 256) {      // 64 rows * 128 float4s
        int jl = f >> 7;
        int k  = (f & 127) << 2;
        float4 v = *reinterpret_cast<const float4*>(&Wh[(size_t)(j0 + jl) * Hh + k]);
        w_s[(k + 0) * 64 + jl] = v.x;
        w_s[(k + 1) * 64 + jl] = v.y;
        w_s[(k + 2) * 64 + jl] = v.z;
        w_s[(k + 3) * 64 + jl] = v.w;
    }
    // ---- h_{-1} = 0
    for (int i = tid; i < H_S_ELEMS; i += 256) h_s[i] = 0.0f;
    __syncthreads();

    const int kg = tid >> 5;            // 0..7  (= warp id: k range [kg*64, kg*64+64))
    const int bt = (tid >> 4) & 1;      // 0..1  (b rows bt*4 .. bt*4+3)
    const int jt = tid & 15;            // 0..15 (j cols jt*4 .. jt*4+3)

    const int o0 = tid;                 // finalize outputs: o = b_l*64 + j_l
    const int o1 = tid + 256;
    const int b_l0 = o0 >> 6, j_l0 = o0 & 63;
    const int b_l1 = o1 >> 6, j_l1 = o1 & 63;

    for (int t = 0; t < Tt; t++) {
        // prefetch xw for this step's two outputs (hoisted over the k-loop)
        const float* xwb = out + ((size_t)t * Bb + b0) * Hh + j0;
        float xw0 = xwb[b_l0 * Hh + j_l0];
        float xw1 = xwb[b_l1 * Hh + j_l1];

        // ---- partial dot products: acc[i][j] = sum_{k in kg range} h[b][k]*Wh[j][k]
        float acc[4][4];
        #pragma unroll
        for (int i = 0; i < 4; i++)
            #pragma unroll
            for (int j = 0; j < 4; j++) acc[i][j] = 0.0f;

        const float* hp = h_s + (bt * 4) * H_S_PITCH + kg * 64;
        const float* wp = w_s + (kg * 64) * 64 + jt * 4;

        #pragma unroll 4
        for (int kq = 0; kq < 64; kq += 4) {
            float4 w0 = *reinterpret_cast<const float4*>(wp + (kq + 0) * 64);
            float4 w1 = *reinterpret_cast<const float4*>(wp + (kq + 1) * 64);
            float4 w2 = *reinterpret_cast<const float4*>(wp + (kq + 2) * 64);
            float4 w3 = *reinterpret_cast<const float4*>(wp + (kq + 3) * 64);
            #pragma unroll
            for (int i = 0; i < 4; i++) {
                float4 hv = *reinterpret_cast<const float4*>(hp + i * H_S_PITCH + kq);
                acc[i][0] += hv.x * w0.x + hv.y * w1.x + hv.z * w2.x + hv.w * w3.x;
                acc[i][1] += hv.x * w0.y + hv.y * w1.y + hv.z * w2.y + hv.w * w3.y;
                acc[i][2] += hv.x * w0.z + hv.y * w1.z + hv.z * w2.z + hv.w * w3.z;
                acc[i][3] += hv.x * w0.w + hv.y * w1.w + hv.z * w2.w + hv.w * w3.w;
            }
        }

        // ---- cross-kg reduction via smem
        float* rp = red + kg * 512 + (bt * 4) * 64 + jt * 4;
        #pragma unroll
        for (int i = 0; i < 4; i++)
            *reinterpret_cast<float4*>(rp + i * 64) =
                make_float4(acc[i][0], acc[i][1], acc[i][2], acc[i][3]);
        __syncthreads();

        float s0 = 0.0f, s1 = 0.0f;
        #pragma unroll
        for (int g = 0; g < 8; g++) {
            s0 += red[g * 512 + o0];
            s1 += red[g * 512 + o1];
        }

        float h0 = tanh_acc(xw0 + s0);
        float h1 = tanh_acc(xw1 + s1);

        // write h_t over xw in d_out[t]
        float* ob = out + ((size_t)t * Bb + b0) * Hh + j0;
        ob[b_l0 * Hh + j_l0] = h0;
        ob[b_l1 * Hh + j_l1] = h1;
        if (t == Tt - 1) {   // h_final tail
            float* tb = out + TBH + (size_t)b0 * Hh + j0;
            tb[b_l0 * Hh + j_l0] = h0;
            tb[b_l1 * Hh + j_l1] = h1;
        }

        // ---- cluster barrier: release our h slice, acquire peers' slices
        asm volatile("barrier.cluster.arrive.aligned;" ::: "memory");
        asm volatile("barrier.cluster.wait.aligned;"   ::: "memory");

        // ---- reload full h_t for our 8 batch rows (16 KB from L2) into h_s
        const float* hg = out + ((size_t)t * Bb + b0) * Hh;
        #pragma unroll
        for (int r = 0; r < 4; r++) {
            int f = tid + r * 256;           // float4 index 0..1023
            int b = f >> 7;                  // 0..7
            int k = (f & 127) << 2;          // 0..508
            float4 v = *reinterpret_cast<const float4*>(hg + (size_t)b * Hh + k);
            *reinterpret_cast<float4*>(h_s + b * H_S_PITCH + k) = v;
        }
        __syncthreads();
    }
}

// =========================================================================
// launcher
// =========================================================================
extern "C" void kernel_launch(void* const* d_in, const int* in_sizes, int n_in,
                              void* d_out, int out_size)
{
    const float* x  = (const float*)d_in[0];   // [T, B, I]
    const float* Wi = (const float*)d_in[1];   // [H, I]
    const float* Wh = (const float*)d_in[2];   // [H, H]
    float* out = (float*)d_out;                // [T*B*H] output  +  [B*H] h_final

    (void)in_sizes; (void)n_in; (void)out_size;

    // Phase 1: xw = x @ Wi^T written into out[0 : T*B*H)
    xw_gemm_kernel<<<(Tt * Bb / 128) * (Hh / 128), 256>>>(x, Wi, out);

    // Phase 2: recurrent scan in place (16 clusters of 8 CTAs)
    cudaFuncSetAttribute(rnn_scan_kernel,
                         cudaFuncAttributeMaxDynamicSharedMemorySize,
                         SCAN_SMEM_BYTES);
    rnn_scan_kernel<<<128, 256, SCAN_SMEM_BYTES>>>(Wh, out);
}